// round 8
// baseline (speedup 1.0000x reference)
#include <cuda_runtime.h>
#include <cuda_fp16.h>
#include <math.h>
#include <stdint.h>

// Problem constants
#define M_ROWS   16384      // B*S
#define E_DIM    768
#define NQ       8
#define FFN_DIM  3072
#define LN_EPS   1e-5f

// ---------------------------------------------------------------------------
// Scratch (device globals: no cudaMalloc allowed)
// ---------------------------------------------------------------------------
__device__ __half g_cx [M_ROWS * E_DIM];    // cos(x + rx), fp16
__device__ float  g_z  [M_ROWS * E_DIM];    // pre-LN1
__device__ float  g_x1 [M_ROWS * E_DIM];    // LN1 output
__device__ float  g_q  [M_ROWS * NQ];
__device__ __half g_h  [M_ROWS * FFN_DIM];  // relu(q@W1+b1), fp16
__device__ float  g_f  [M_ROWS * E_DIM];    // pre-LN2
__device__ __half g_WcT[E_DIM * E_DIM];     // Wc^T, fp16
__device__ __half g_W2T[E_DIM * FFN_DIM];   // W2^T, fp16

// ---------------------------------------------------------------------------
// Helpers (baseline PTX only — compute_103 has no 'a' features)
// ---------------------------------------------------------------------------
__device__ __forceinline__ uint32_t smem_u32(const void* p) {
    uint32_t a;
    asm("{ .reg .u64 t; cvta.to.shared.u64 t, %1; cvt.u32.u64 %0, t; }"
        : "=r"(a) : "l"(p));
    return a;
}

__device__ __forceinline__ void cp16(uint32_t s, const void* g) {
    asm volatile("cp.async.ca.shared.global [%0], [%1], 16;" :: "r"(s), "l"(g));
}
#define CP_COMMIT() asm volatile("cp.async.commit_group;" ::: "memory")
#define CP_WAIT(n)  asm volatile("cp.async.wait_group %0;" :: "n"(n) : "memory")

__device__ __forceinline__ void ldsm4(uint32_t* r, uint32_t addr) {
    asm volatile("ldmatrix.sync.aligned.m8n8.x4.shared.b16 {%0,%1,%2,%3}, [%4];"
        : "=r"(r[0]), "=r"(r[1]), "=r"(r[2]), "=r"(r[3]) : "r"(addr));
}

__device__ __forceinline__ void mma16816(float* c, const uint32_t* a,
                                         uint32_t b0, uint32_t b1) {
    asm volatile(
        "mma.sync.aligned.m16n8k16.row.col.f32.f16.f16.f32 "
        "{%0,%1,%2,%3}, {%4,%5,%6,%7}, {%8,%9}, {%0,%1,%2,%3};"
        : "+f"(c[0]), "+f"(c[1]), "+f"(c[2]), "+f"(c[3])
        : "r"(a[0]), "r"(a[1]), "r"(a[2]), "r"(a[3]), "r"(b0), "r"(b1));
}

// ---------------------------------------------------------------------------
// fp16 tensor-core GEMM:
//   C[M, 768] = A[M, K] @ Bt[768, K]^T + bias + res
// CTA: 256 threads (8 warps, 4x2 grid), tile 128(M) x 128(N),
// warp tile 32(M) x 64(N)  -> acc = 64 regs/thread, ~120 total,
// so 2 CTAs/SM = 16 warps/SM (4 per SMSP).
// KT=32, 4-stage cp.async pipeline, ONE __syncthreads per K-tile.
// Smem rows: 64B payload, 80B stride (16B-aligned cp.async; r*20 words mod 32
// tiles all banks -> conflict-free ldmatrix).
// ---------------------------------------------------------------------------
#define KT        32
#define ROW_B     80                        // smem row stride bytes
#define A_BYTES   (128 * ROW_B)
#define B_BYTES   (128 * ROW_B)
#define STAGE_BYTES (A_BYTES + B_BYTES)     // 20480
#define NSTAGE    4
#define SMEM_BYTES  (NSTAGE * STAGE_BYTES)  // 81920

__global__ void __launch_bounds__(256, 2)
gemm_mma_kernel(const __half* __restrict__ A, const __half* __restrict__ Bt,
                const float* __restrict__ bias, const float* __restrict__ res,
                float* __restrict__ C, int K, int NK)
{
    extern __shared__ char smem[];
    const uint32_t sbase = smem_u32(smem);

    const int tid  = threadIdx.x;
    const int w    = tid >> 5, lane = tid & 31;
    const int g    = lane >> 2, tg = lane & 3;
    const int row0 = blockIdx.y * 128;
    const int col0 = blockIdx.x * 128;
    const int wm   = (w >> 1) * 32;         // 0,32,64,96
    const int wn   = (w & 1) * 64;          // 0,64

    // ldmatrix lane addressing
    const int lrow = lane & 15;
    const int lsel = lane >> 4;

    // cp.async loader: thread -> (row tid>>2 in 0..63, 16B-chunk tid&3)
    const int crow = tid >> 2;              // 0..63
    const int cchk = tid & 3;               // 0..3
    const __half* Ag = A  + (size_t)(row0 + crow) * K + cchk * 8;
    const __half* Bg = Bt + (size_t)(col0 + crow) * K + cchk * 8;

    float acc[2][8][4];
    #pragma unroll
    for (int i = 0; i < 2; i++)
        #pragma unroll
        for (int j = 0; j < 8; j++)
            #pragma unroll
            for (int v = 0; v < 4; v++) acc[i][j][v] = 0.f;

    const uint32_t so = (uint32_t)crow * ROW_B + (uint32_t)cchk * 16u;

    auto issue = [&](int kt) {
        const int s = kt & (NSTAGE - 1);
        const int k0 = kt * KT;
        const uint32_t sA = sbase + (uint32_t)s * STAGE_BYTES;
        const uint32_t sB = sA + A_BYTES;
        #pragma unroll
        for (int p = 0; p < 2; p++)
            cp16(sA + so + (uint32_t)(64 * p) * ROW_B,
                 Ag + (size_t)(64 * p) * K + k0);
        #pragma unroll
        for (int p = 0; p < 2; p++)
            cp16(sB + so + (uint32_t)(64 * p) * ROW_B,
                 Bg + (size_t)(64 * p) * K + k0);
        CP_COMMIT();
    };

    issue(0); issue(1); issue(2);

    for (int kt = 0; kt < NK; kt++) {
        const int s = kt & (NSTAGE - 1);
        CP_WAIT(2);                          // group kt complete
        __syncthreads();                     // all threads see stage s
        // prefetch into stage (kt+3)%4 — last read in iter kt-1, ordered by sync
        if (kt + 3 < NK) issue(kt + 3); else CP_COMMIT();

        const uint32_t sA = sbase + (uint32_t)s * STAGE_BYTES;
        const uint32_t sB = sA + A_BYTES;
        const uint32_t aB = sA + (uint32_t)(wm + lrow) * ROW_B + (uint32_t)lsel * 16u;
        const uint32_t bB = sB + (uint32_t)(wn + lrow) * ROW_B + (uint32_t)lsel * 16u;

        #pragma unroll
        for (int t2 = 0; t2 < 2; t2++) {     // 2 x k16 per stage
            uint32_t a[2][4];
            #pragma unroll
            for (int i = 0; i < 2; i++)
                ldsm4(a[i], aB + (uint32_t)(16 * i) * ROW_B + (uint32_t)t2 * 32u);
            uint32_t b[4][4];
            #pragma unroll
            for (int jj = 0; jj < 4; jj++)
                ldsm4(b[jj], bB + (uint32_t)(16 * jj) * ROW_B + (uint32_t)t2 * 32u);

            #pragma unroll
            for (int i = 0; i < 2; i++)
                #pragma unroll
                for (int j = 0; j < 8; j++) {
                    const int jj = j >> 1, odd = j & 1;
                    mma16816(acc[i][j], a[i], b[jj][odd], b[jj][2 + odd]);
                }
        }
        // no second barrier: next iter's sync orders consumption vs refill
    }

    // Epilogue: + bias + res -> C (float2, cols even)
    float2 bj[8];
    #pragma unroll
    for (int j = 0; j < 8; j++)
        bj[j] = *(const float2*)(bias + col0 + wn + 8 * j + 2 * tg);

    #pragma unroll
    for (int i = 0; i < 2; i++) {
        const int r0 = row0 + wm + 16 * i + g;
        const int r1 = r0 + 8;
        #pragma unroll
        for (int j = 0; j < 8; j++) {
            const int c = col0 + wn + 8 * j + 2 * tg;
            const size_t i0 = (size_t)r0 * E_DIM + c;
            const size_t i1 = (size_t)r1 * E_DIM + c;
            float2 rv0 = *(const float2*)(res + i0);
            float2 rv1 = *(const float2*)(res + i1);
            float2 o0, o1;
            o0.x = acc[i][j][0] + bj[j].x + rv0.x;
            o0.y = acc[i][j][1] + bj[j].y + rv0.y;
            o1.x = acc[i][j][2] + bj[j].x + rv1.x;
            o1.y = acc[i][j][3] + bj[j].y + rv1.y;
            *(float2*)(C + i0) = o0;
            *(float2*)(C + i1) = o1;
        }
    }
}

// ---------------------------------------------------------------------------
// cos(x + rx) precompute -> fp16 (8 elems/thread, 16B store)
// ---------------------------------------------------------------------------
__global__ void __launch_bounds__(256)
cosx_kernel(const float* __restrict__ x, const float* __restrict__ rx,
            __half* __restrict__ cx)
{
    const int i = blockIdx.x * 256 + threadIdx.x;       // 8-elem index
    float4 v0 = ((const float4*)x)[2 * i];
    float4 v1 = ((const float4*)x)[2 * i + 1];
    const int e = (i * 8) & 63;
    __half2 h[4];
    h[0] = __floats2half2_rn(cosf(v0.x + rx[e + 0]), cosf(v0.y + rx[e + 1]));
    h[1] = __floats2half2_rn(cosf(v0.z + rx[e + 2]), cosf(v0.w + rx[e + 3]));
    h[2] = __floats2half2_rn(cosf(v1.x + rx[e + 4]), cosf(v1.y + rx[e + 5]));
    h[3] = __floats2half2_rn(cosf(v1.z + rx[e + 6]), cosf(v1.w + rx[e + 7]));
    ((uint4*)cx)[i] = *(const uint4*)h;
}

// ---------------------------------------------------------------------------
// Transpose: in R x C (fp32) -> out C x R (fp16)
// ---------------------------------------------------------------------------
__global__ void __launch_bounds__(256)
transpose_kernel(const float* __restrict__ in, __half* __restrict__ out, int R, int C)
{
    __shared__ float t[32][33];
    const int c0 = blockIdx.x * 32, r0 = blockIdx.y * 32;
    #pragma unroll
    for (int j = 0; j < 4; j++)
        t[threadIdx.y + j * 8][threadIdx.x] =
            in[(size_t)(r0 + threadIdx.y + j * 8) * C + (c0 + threadIdx.x)];
    __syncthreads();
    #pragma unroll
    for (int j = 0; j < 4; j++)
        out[(size_t)(c0 + threadIdx.y + j * 8) * R + (r0 + threadIdx.x)] =
            __float2half_rn(t[threadIdx.x][threadIdx.y + j * 8]);
}

// ---------------------------------------------------------------------------
// Row LayerNorm over E=768 (one block per row); optionally writes q
// ---------------------------------------------------------------------------
template <bool WRITE_Q>
__global__ void __launch_bounds__(256)
ln_kernel(const float* __restrict__ in, const float* __restrict__ g,
          const float* __restrict__ b, const float* __restrict__ ry,
          float* __restrict__ out, float* __restrict__ q)
{
    const int m   = blockIdx.x;
    const int tid = threadIdx.x;
    const float* row = in + (size_t)m * E_DIM;

    float v[3];
    float s = 0.f, ss = 0.f;
    #pragma unroll
    for (int j = 0; j < 3; j++) {
        v[j] = row[tid + j * 256];
        s  += v[j];
        ss += v[j] * v[j];
    }
    #pragma unroll
    for (int o = 16; o > 0; o >>= 1) {
        s  += __shfl_xor_sync(0xffffffffu, s,  o);
        ss += __shfl_xor_sync(0xffffffffu, ss, o);
    }
    __shared__ float red[16];
    const int warp = tid >> 5, lane = tid & 31;
    if (lane == 0) { red[warp] = s; red[warp + 8] = ss; }
    __syncthreads();
    if (tid == 0) {
        float S = 0.f, SS = 0.f;
        #pragma unroll
        for (int w = 0; w < 8; w++) { S += red[w]; SS += red[w + 8]; }
        red[0] = S; red[8] = SS;
    }
    __syncthreads();

    const float mu  = red[0] * (1.f / E_DIM);
    const float var = red[8] * (1.f / E_DIM) - mu * mu;
    const float inv = rsqrtf(var + LN_EPS);

    #pragma unroll
    for (int j = 0; j < 3; j++) {
        const int e = tid + j * 256;
        const float y = (v[j] - mu) * inv * g[e] + b[e];
        out[(size_t)m * E_DIM + e] = y;
        if (WRITE_Q && j == 0 && tid < NQ)
            q[(size_t)m * NQ + tid] = cosf(y) * cosf(ry[tid]);
    }
}

// ---------------------------------------------------------------------------
// FFN first layer (tiled): h = relu(q @ W1 + b1) -> fp16.
// ---------------------------------------------------------------------------
__global__ void __launch_bounds__(256)
ffn1_kernel(const float* __restrict__ q, const float* __restrict__ W1,
            const float* __restrict__ b1, __half* __restrict__ h)
{
    __shared__ float w1s[NQ][1024];
    __shared__ float b1s[1024];
    __shared__ float qs[256][NQ];

    const int col0 = blockIdx.x * 1024;
    const int m0   = blockIdx.y * 256;
    const int tid  = threadIdx.x;

    #pragma unroll
    for (int i = 0; i < NQ; i++)
        *(float4*)&w1s[i][tid * 4] =
            *(const float4*)(W1 + (size_t)i * FFN_DIM + col0 + tid * 4);
    *(float4*)&b1s[tid * 4] = *(const float4*)(b1 + col0 + tid * 4);
    {
        const int r = tid;
        float2 q01 = *(const float2*)(q + (size_t)(m0 + r) * NQ + 0);
        float2 q23 = *(const float2*)(q + (size_t)(m0 + r) * NQ + 2);
        float2 q45 = *(const float2*)(q + (size_t)(m0 + r) * NQ + 4);
        float2 q67 = *(const float2*)(q + (size_t)(m0 + r) * NQ + 6);
        qs[r][0] = q01.x; qs[r][1] = q01.y;
        qs[r][2] = q23.x; qs[r][3] = q23.y;
        qs[r][4] = q45.x; qs[r][5] = q45.y;
        qs[r][6] = q67.x; qs[r][7] = q67.y;
    }
    __syncthreads();

    float4 wr[NQ];
    #pragma unroll
    for (int i = 0; i < NQ; i++) wr[i] = *(float4*)&w1s[i][tid * 4];
    const float4 bb = *(float4*)&b1s[tid * 4];

    __half* hp = h + (size_t)m0 * FFN_DIM + col0 + tid * 4;
    for (int r = 0; r < 256; r++) {
        float4 acc = bb;
        #pragma unroll
        for (int i = 0; i < NQ; i++) {
            const float qv = qs[r][i];
            acc.x = fmaf(qv, wr[i].x, acc.x);
            acc.y = fmaf(qv, wr[i].y, acc.y);
            acc.z = fmaf(qv, wr[i].z, acc.z);
            acc.w = fmaf(qv, wr[i].w, acc.w);
        }
        __half2 p0 = __floats2half2_rn(fmaxf(acc.x, 0.f), fmaxf(acc.y, 0.f));
        __half2 p1 = __floats2half2_rn(fmaxf(acc.z, 0.f), fmaxf(acc.w, 0.f));
        uint2 pk = make_uint2(*(uint32_t*)&p0, *(uint32_t*)&p1);
        *(uint2*)(hp + (size_t)r * FFN_DIM) = pk;
    }
}

// ---------------------------------------------------------------------------
// Launch
// ---------------------------------------------------------------------------
extern "C" void kernel_launch(void* const* d_in, const int* in_sizes, int n_in,
                              void* d_out, int out_size)
{
    const float* x   = (const float*)d_in[0];
    const float* rx  = (const float*)d_in[1];
    const float* ry  = (const float*)d_in[2];
    const float* Wc  = (const float*)d_in[3];
    const float* bc  = (const float*)d_in[4];
    const float* W1  = (const float*)d_in[5];
    const float* b1  = (const float*)d_in[6];
    const float* W2  = (const float*)d_in[7];
    const float* b2  = (const float*)d_in[8];
    const float* g1  = (const float*)d_in[9];
    const float* be1 = (const float*)d_in[10];
    const float* g2  = (const float*)d_in[11];
    const float* be2 = (const float*)d_in[12];
    float* out = (float*)d_out;

    __half *cx, *h, *WcT, *W2T;
    float *z, *x1, *q, *f;
    cudaGetSymbolAddress((void**)&cx,  g_cx);
    cudaGetSymbolAddress((void**)&z,   g_z);
    cudaGetSymbolAddress((void**)&x1,  g_x1);
    cudaGetSymbolAddress((void**)&q,   g_q);
    cudaGetSymbolAddress((void**)&h,   g_h);
    cudaGetSymbolAddress((void**)&f,   g_f);
    cudaGetSymbolAddress((void**)&WcT, g_WcT);
    cudaGetSymbolAddress((void**)&W2T, g_W2T);

    cudaFuncSetAttribute(gemm_mma_kernel,
                         cudaFuncAttributeMaxDynamicSharedMemorySize, SMEM_BYTES);

    // 0) weight transposes (fp16) + cos precompute (fp16)
    transpose_kernel<<<dim3(E_DIM / 32, E_DIM / 32), dim3(32, 8)>>>(Wc, WcT, E_DIM, E_DIM);
    transpose_kernel<<<dim3(E_DIM / 32, FFN_DIM / 32), dim3(32, 8)>>>(W2, W2T, FFN_DIM, E_DIM);
    cosx_kernel<<<(M_ROWS * E_DIM / 8) / 256, 256>>>(x, rx, cx);

    // 1) z = cos(x+rx) @ Wc + bc + x        (fp16 mma + ldmatrix)
    gemm_mma_kernel<<<dim3(E_DIM / 128, M_ROWS / 128), 256, SMEM_BYTES>>>(
        cx, WcT, bc, x, z, E_DIM, E_DIM / KT);

    // 2) x1 = LN(z); q = cos(x1[:, :8]) * cos(ry)
    ln_kernel<true><<<M_ROWS, 256>>>(z, g1, be1, ry, x1, q);

    // 3) h = relu(q @ W1 + b1)  -> fp16
    ffn1_kernel<<<dim3(FFN_DIM / 1024, M_ROWS / 256), 256>>>(q, W1, b1, h);

    // 4) f = h @ W2 + b2 + x1               (fp16 mma + ldmatrix)
    gemm_mma_kernel<<<dim3(E_DIM / 128, M_ROWS / 128), 256, SMEM_BYTES>>>(
        h, W2T, b2, x1, f, FFN_DIM, FFN_DIM / KT);

    // 5) out = LN(f)
    ln_kernel<false><<<M_ROWS, 256>>>(f, g2, be2, nullptr, out, nullptr);
}

// round 9
// speedup vs baseline: 1.0984x; 1.0984x over previous
#include <cuda_runtime.h>
#include <cuda_fp16.h>
#include <math.h>
#include <stdint.h>

// Problem constants
#define M_ROWS   16384      // B*S
#define E_DIM    768
#define NQ       8
#define FFN_DIM  3072
#define LN_EPS   1e-5f

// ---------------------------------------------------------------------------
// Scratch (device globals: no cudaMalloc allowed)
// ---------------------------------------------------------------------------
__device__ __half g_cx [M_ROWS * E_DIM];    // cos(x + rx), fp16
__device__ float  g_z  [M_ROWS * E_DIM];    // pre-LN1
__device__ float  g_x1 [M_ROWS * E_DIM];    // LN1 output
__device__ float  g_q  [M_ROWS * NQ];
__device__ __half g_h  [M_ROWS * FFN_DIM];  // relu(q@W1+b1), fp16
__device__ float  g_f  [M_ROWS * E_DIM];    // pre-LN2
__device__ __half g_WcT[E_DIM * E_DIM];     // Wc^T, fp16
__device__ __half g_W2T[E_DIM * FFN_DIM];   // W2^T, fp16

// ---------------------------------------------------------------------------
// Helpers (baseline PTX only — compute_103 has no 'a' features)
// ---------------------------------------------------------------------------
__device__ __forceinline__ uint32_t smem_u32(const void* p) {
    uint32_t a;
    asm("{ .reg .u64 t; cvta.to.shared.u64 t, %1; cvt.u32.u64 %0, t; }"
        : "=r"(a) : "l"(p));
    return a;
}

__device__ __forceinline__ void cp16(uint32_t s, const void* g) {
    asm volatile("cp.async.ca.shared.global [%0], [%1], 16;" :: "r"(s), "l"(g));
}
#define CP_COMMIT() asm volatile("cp.async.commit_group;" ::: "memory")
#define CP_WAIT(n)  asm volatile("cp.async.wait_group %0;" :: "n"(n) : "memory")

__device__ __forceinline__ void ldsm4(uint32_t* r, uint32_t addr) {
    asm volatile("ldmatrix.sync.aligned.m8n8.x4.shared.b16 {%0,%1,%2,%3}, [%4];"
        : "=r"(r[0]), "=r"(r[1]), "=r"(r[2]), "=r"(r[3]) : "r"(addr));
}

__device__ __forceinline__ void mma16816(float* c, const uint32_t* a,
                                         uint32_t b0, uint32_t b1) {
    asm volatile(
        "mma.sync.aligned.m16n8k16.row.col.f32.f16.f16.f32 "
        "{%0,%1,%2,%3}, {%4,%5,%6,%7}, {%8,%9}, {%0,%1,%2,%3};"
        : "+f"(c[0]), "+f"(c[1]), "+f"(c[2]), "+f"(c[3])
        : "r"(a[0]), "r"(a[1]), "r"(a[2]), "r"(a[3]), "r"(b0), "r"(b1));
}

// ---------------------------------------------------------------------------
// fp16 tensor-core GEMM:
//   C[M, 768] = A[M, K] @ Bt[768, K]^T + bias + res
// CTA: 256 threads (8 warps, 4x2), tile 256(M) x 128(N), warp tile 64x64
//   (max smem reuse: each A/B smem byte read by only 2 warps).
// KT=64, 3-stage cp.async pipeline, ONE __syncthreads per K-tile,
// fragment double-buffering across the 4 k16 steps (LDSM latency hidden).
// Smem rows: 128B payload, 144B stride (16B-aligned; r*36 words mod 32
// tiles the banks -> conflict-free ldmatrix).
// ---------------------------------------------------------------------------
#define KT        64
#define ROW_B     144                       // smem row stride bytes
#define A_BYTES   (256 * ROW_B)             // 36864
#define B_BYTES   (128 * ROW_B)             // 18432
#define STAGE_BYTES (A_BYTES + B_BYTES)     // 55296
#define NSTAGE    3
#define SMEM_BYTES  (NSTAGE * STAGE_BYTES)  // 165888

__global__ void __launch_bounds__(256, 1)
gemm_mma_kernel(const __half* __restrict__ A, const __half* __restrict__ Bt,
                const float* __restrict__ bias, const float* __restrict__ res,
                float* __restrict__ C, int K, int NK)
{
    extern __shared__ char smem[];
    const uint32_t sbase = smem_u32(smem);

    const int tid  = threadIdx.x;
    const int w    = tid >> 5, lane = tid & 31;
    const int g    = lane >> 2, tg = lane & 3;
    const int row0 = blockIdx.y * 256;
    const int col0 = blockIdx.x * 128;
    const int wm   = (w >> 1) * 64;         // 0,64,128,192
    const int wn   = (w & 1) * 64;          // 0,64

    // ldmatrix lane addressing
    const int lrow = lane & 15;
    const int lsel = lane >> 4;

    // cp.async loader: thread -> (row tid>>3 in 0..31, 16B-chunk tid&7)
    const int crow = tid >> 3;              // 0..31
    const int cchk = tid & 7;               // 0..7
    const __half* Ag = A  + (size_t)(row0 + crow) * K + cchk * 8;
    const __half* Bg = Bt + (size_t)(col0 + crow) * K + cchk * 8;

    float acc[4][8][4];
    #pragma unroll
    for (int i = 0; i < 4; i++)
        #pragma unroll
        for (int j = 0; j < 8; j++)
            #pragma unroll
            for (int v = 0; v < 4; v++) acc[i][j][v] = 0.f;

    const uint32_t so = (uint32_t)crow * ROW_B + (uint32_t)cchk * 16u;

    auto issue = [&](int kt) {
        const int s = kt % NSTAGE;
        const int k0 = kt * KT;
        const uint32_t sA = sbase + (uint32_t)s * STAGE_BYTES;
        const uint32_t sB = sA + A_BYTES;
        #pragma unroll
        for (int p = 0; p < 8; p++)
            cp16(sA + so + (uint32_t)(32 * p) * ROW_B,
                 Ag + (size_t)(32 * p) * K + k0);
        #pragma unroll
        for (int p = 0; p < 4; p++)
            cp16(sB + so + (uint32_t)(32 * p) * ROW_B,
                 Bg + (size_t)(32 * p) * K + k0);
        CP_COMMIT();
    };

    issue(0); issue(1);

    uint32_t af[2][4][4];   // [buf][i][reg] A fragments (4 m16 tiles)
    uint32_t bf[2][4][4];   // [buf][jj][reg] B fragments (4 n16 tiles)

    for (int kt = 0; kt < NK; kt++) {
        const int s = kt % NSTAGE;
        CP_WAIT(1);                          // positional: all except newest done
        __syncthreads();                     // stage s visible to all warps
        // one commit per iteration keeps wait_group arithmetic exact
        if (kt + 2 < NK) issue(kt + 2); else CP_COMMIT();

        const uint32_t sA = sbase + (uint32_t)s * STAGE_BYTES;
        const uint32_t sB = sA + A_BYTES;
        const uint32_t aB = sA + (uint32_t)(wm + lrow) * ROW_B + (uint32_t)lsel * 16u;
        const uint32_t bB = sB + (uint32_t)(wn + lrow) * ROW_B + (uint32_t)lsel * 16u;

        // prime fragments for k-step 0
        #pragma unroll
        for (int i = 0; i < 4; i++)
            ldsm4(af[0][i], aB + (uint32_t)(16 * i) * ROW_B);
        #pragma unroll
        for (int jj = 0; jj < 4; jj++)
            ldsm4(bf[0][jj], bB + (uint32_t)(16 * jj) * ROW_B);

        #pragma unroll
        for (int t2 = 0; t2 < 4; t2++) {     // 4 x k16 per stage
            const int cur = t2 & 1, nxt = cur ^ 1;
            if (t2 < 3) {                    // prefetch next k-step's fragments
                const uint32_t ko = (uint32_t)(t2 + 1) * 32u;
                #pragma unroll
                for (int i = 0; i < 4; i++)
                    ldsm4(af[nxt][i], aB + (uint32_t)(16 * i) * ROW_B + ko);
                #pragma unroll
                for (int jj = 0; jj < 4; jj++)
                    ldsm4(bf[nxt][jj], bB + (uint32_t)(16 * jj) * ROW_B + ko);
            }
            #pragma unroll
            for (int i = 0; i < 4; i++)
                #pragma unroll
                for (int j = 0; j < 8; j++) {
                    const int jj = j >> 1, odd = j & 1;
                    mma16816(acc[i][j], af[cur][i],
                             bf[cur][jj][odd], bf[cur][jj][2 + odd]);
                }
        }
        // single barrier per tile: next iter's sync orders reads vs refill
    }

    // Epilogue: + bias + res -> C (float2, cols even)
    float2 bj[8];
    #pragma unroll
    for (int j = 0; j < 8; j++)
        bj[j] = *(const float2*)(bias + col0 + wn + 8 * j + 2 * tg);

    #pragma unroll
    for (int i = 0; i < 4; i++) {
        const int r0 = row0 + wm + 16 * i + g;
        const int r1 = r0 + 8;
        #pragma unroll
        for (int j = 0; j < 8; j++) {
            const int c = col0 + wn + 8 * j + 2 * tg;
            const size_t i0 = (size_t)r0 * E_DIM + c;
            const size_t i1 = (size_t)r1 * E_DIM + c;
            float2 rv0 = *(const float2*)(res + i0);
            float2 rv1 = *(const float2*)(res + i1);
            float2 o0, o1;
            o0.x = acc[i][j][0] + bj[j].x + rv0.x;
            o0.y = acc[i][j][1] + bj[j].y + rv0.y;
            o1.x = acc[i][j][2] + bj[j].x + rv1.x;
            o1.y = acc[i][j][3] + bj[j].y + rv1.y;
            *(float2*)(C + i0) = o0;
            *(float2*)(C + i1) = o1;
        }
    }
}

// ---------------------------------------------------------------------------
// cos(x + rx) precompute -> fp16 (8 elems/thread, 16B store)
// ---------------------------------------------------------------------------
__global__ void __launch_bounds__(256)
cosx_kernel(const float* __restrict__ x, const float* __restrict__ rx,
            __half* __restrict__ cx)
{
    const int i = blockIdx.x * 256 + threadIdx.x;       // 8-elem index
    float4 v0 = ((const float4*)x)[2 * i];
    float4 v1 = ((const float4*)x)[2 * i + 1];
    const int e = (i * 8) & 63;
    __half2 h[4];
    h[0] = __floats2half2_rn(cosf(v0.x + rx[e + 0]), cosf(v0.y + rx[e + 1]));
    h[1] = __floats2half2_rn(cosf(v0.z + rx[e + 2]), cosf(v0.w + rx[e + 3]));
    h[2] = __floats2half2_rn(cosf(v1.x + rx[e + 4]), cosf(v1.y + rx[e + 5]));
    h[3] = __floats2half2_rn(cosf(v1.z + rx[e + 6]), cosf(v1.w + rx[e + 7]));
    ((uint4*)cx)[i] = *(const uint4*)h;
}

// ---------------------------------------------------------------------------
// Transpose: in R x C (fp32) -> out C x R (fp16)
// ---------------------------------------------------------------------------
__global__ void __launch_bounds__(256)
transpose_kernel(const float* __restrict__ in, __half* __restrict__ out, int R, int C)
{
    __shared__ float t[32][33];
    const int c0 = blockIdx.x * 32, r0 = blockIdx.y * 32;
    #pragma unroll
    for (int j = 0; j < 4; j++)
        t[threadIdx.y + j * 8][threadIdx.x] =
            in[(size_t)(r0 + threadIdx.y + j * 8) * C + (c0 + threadIdx.x)];
    __syncthreads();
    #pragma unroll
    for (int j = 0; j < 4; j++)
        out[(size_t)(c0 + threadIdx.y + j * 8) * R + (r0 + threadIdx.x)] =
            __float2half_rn(t[threadIdx.x][threadIdx.y + j * 8]);
}

// ---------------------------------------------------------------------------
// Row LayerNorm over E=768 (one block per row); optionally writes q
// ---------------------------------------------------------------------------
template <bool WRITE_Q>
__global__ void __launch_bounds__(256)
ln_kernel(const float* __restrict__ in, const float* __restrict__ g,
          const float* __restrict__ b, const float* __restrict__ ry,
          float* __restrict__ out, float* __restrict__ q)
{
    const int m   = blockIdx.x;
    const int tid = threadIdx.x;
    const float* row = in + (size_t)m * E_DIM;

    float v[3];
    float s = 0.f, ss = 0.f;
    #pragma unroll
    for (int j = 0; j < 3; j++) {
        v[j] = row[tid + j * 256];
        s  += v[j];
        ss += v[j] * v[j];
    }
    #pragma unroll
    for (int o = 16; o > 0; o >>= 1) {
        s  += __shfl_xor_sync(0xffffffffu, s,  o);
        ss += __shfl_xor_sync(0xffffffffu, ss, o);
    }
    __shared__ float red[16];
    const int warp = tid >> 5, lane = tid & 31;
    if (lane == 0) { red[warp] = s; red[warp + 8] = ss; }
    __syncthreads();
    if (tid == 0) {
        float S = 0.f, SS = 0.f;
        #pragma unroll
        for (int w = 0; w < 8; w++) { S += red[w]; SS += red[w + 8]; }
        red[0] = S; red[8] = SS;
    }
    __syncthreads();

    const float mu  = red[0] * (1.f / E_DIM);
    const float var = red[8] * (1.f / E_DIM) - mu * mu;
    const float inv = rsqrtf(var + LN_EPS);

    #pragma unroll
    for (int j = 0; j < 3; j++) {
        const int e = tid + j * 256;
        const float y = (v[j] - mu) * inv * g[e] + b[e];
        out[(size_t)m * E_DIM + e] = y;
        if (WRITE_Q && j == 0 && tid < NQ)
            q[(size_t)m * NQ + tid] = cosf(y) * cosf(ry[tid]);
    }
}

// ---------------------------------------------------------------------------
// FFN first layer (tiled): h = relu(q @ W1 + b1) -> fp16.
// ---------------------------------------------------------------------------
__global__ void __launch_bounds__(256)
ffn1_kernel(const float* __restrict__ q, const float* __restrict__ W1,
            const float* __restrict__ b1, __half* __restrict__ h)
{
    __shared__ float w1s[NQ][1024];
    __shared__ float b1s[1024];
    __shared__ float qs[256][NQ];

    const int col0 = blockIdx.x * 1024;
    const int m0   = blockIdx.y * 256;
    const int tid  = threadIdx.x;

    #pragma unroll
    for (int i = 0; i < NQ; i++)
        *(float4*)&w1s[i][tid * 4] =
            *(const float4*)(W1 + (size_t)i * FFN_DIM + col0 + tid * 4);
    *(float4*)&b1s[tid * 4] = *(const float4*)(b1 + col0 + tid * 4);
    {
        const int r = tid;
        float2 q01 = *(const float2*)(q + (size_t)(m0 + r) * NQ + 0);
        float2 q23 = *(const float2*)(q + (size_t)(m0 + r) * NQ + 2);
        float2 q45 = *(const float2*)(q + (size_t)(m0 + r) * NQ + 4);
        float2 q67 = *(const float2*)(q + (size_t)(m0 + r) * NQ + 6);
        qs[r][0] = q01.x; qs[r][1] = q01.y;
        qs[r][2] = q23.x; qs[r][3] = q23.y;
        qs[r][4] = q45.x; qs[r][5] = q45.y;
        qs[r][6] = q67.x; qs[r][7] = q67.y;
    }
    __syncthreads();

    float4 wr[NQ];
    #pragma unroll
    for (int i = 0; i < NQ; i++) wr[i] = *(float4*)&w1s[i][tid * 4];
    const float4 bb = *(float4*)&b1s[tid * 4];

    __half* hp = h + (size_t)m0 * FFN_DIM + col0 + tid * 4;
    for (int r = 0; r < 256; r++) {
        float4 acc = bb;
        #pragma unroll
        for (int i = 0; i < NQ; i++) {
            const float qv = qs[r][i];
            acc.x = fmaf(qv, wr[i].x, acc.x);
            acc.y = fmaf(qv, wr[i].y, acc.y);
            acc.z = fmaf(qv, wr[i].z, acc.z);
            acc.w = fmaf(qv, wr[i].w, acc.w);
        }
        __half2 p0 = __floats2half2_rn(fmaxf(acc.x, 0.f), fmaxf(acc.y, 0.f));
        __half2 p1 = __floats2half2_rn(fmaxf(acc.z, 0.f), fmaxf(acc.w, 0.f));
        uint2 pk = make_uint2(*(uint32_t*)&p0, *(uint32_t*)&p1);
        *(uint2*)(hp + (size_t)r * FFN_DIM) = pk;
    }
}

// ---------------------------------------------------------------------------
// Launch
// ---------------------------------------------------------------------------
extern "C" void kernel_launch(void* const* d_in, const int* in_sizes, int n_in,
                              void* d_out, int out_size)
{
    const float* x   = (const float*)d_in[0];
    const float* rx  = (const float*)d_in[1];
    const float* ry  = (const float*)d_in[2];
    const float* Wc  = (const float*)d_in[3];
    const float* bc  = (const float*)d_in[4];
    const float* W1  = (const float*)d_in[5];
    const float* b1  = (const float*)d_in[6];
    const float* W2  = (const float*)d_in[7];
    const float* b2  = (const float*)d_in[8];
    const float* g1  = (const float*)d_in[9];
    const float* be1 = (const float*)d_in[10];
    const float* g2  = (const float*)d_in[11];
    const float* be2 = (const float*)d_in[12];
    float* out = (float*)d_out;

    __half *cx, *h, *WcT, *W2T;
    float *z, *x1, *q, *f;
    cudaGetSymbolAddress((void**)&cx,  g_cx);
    cudaGetSymbolAddress((void**)&z,   g_z);
    cudaGetSymbolAddress((void**)&x1,  g_x1);
    cudaGetSymbolAddress((void**)&q,   g_q);
    cudaGetSymbolAddress((void**)&h,   g_h);
    cudaGetSymbolAddress((void**)&f,   g_f);
    cudaGetSymbolAddress((void**)&WcT, g_WcT);
    cudaGetSymbolAddress((void**)&W2T, g_W2T);

    cudaFuncSetAttribute(gemm_mma_kernel,
                         cudaFuncAttributeMaxDynamicSharedMemorySize, SMEM_BYTES);

    // 0) weight transposes (fp16) + cos precompute (fp16)
    transpose_kernel<<<dim3(E_DIM / 32, E_DIM / 32), dim3(32, 8)>>>(Wc, WcT, E_DIM, E_DIM);
    transpose_kernel<<<dim3(E_DIM / 32, FFN_DIM / 32), dim3(32, 8)>>>(W2, W2T, FFN_DIM, E_DIM);
    cosx_kernel<<<(M_ROWS * E_DIM / 8) / 256, 256>>>(x, rx, cx);

    // 1) z = cos(x+rx) @ Wc + bc + x        (fp16 mma + ldmatrix)
    gemm_mma_kernel<<<dim3(E_DIM / 128, M_ROWS / 256), 256, SMEM_BYTES>>>(
        cx, WcT, bc, x, z, E_DIM, E_DIM / KT);

    // 2) x1 = LN(z); q = cos(x1[:, :8]) * cos(ry)
    ln_kernel<true><<<M_ROWS, 256>>>(z, g1, be1, ry, x1, q);

    // 3) h = relu(q @ W1 + b1)  -> fp16
    ffn1_kernel<<<dim3(FFN_DIM / 1024, M_ROWS / 256), 256>>>(q, W1, b1, h);

    // 4) f = h @ W2 + b2 + x1               (fp16 mma + ldmatrix)
    gemm_mma_kernel<<<dim3(E_DIM / 128, M_ROWS / 256), 256, SMEM_BYTES>>>(
        h, W2T, b2, x1, f, FFN_DIM, FFN_DIM / KT);

    // 5) out = LN(f)
    ln_kernel<false><<<M_ROWS, 256>>>(f, g2, be2, nullptr, out, nullptr);
}

// round 10
// speedup vs baseline: 1.1347x; 1.0331x over previous
#include <cuda_runtime.h>
#include <cuda_fp16.h>
#include <math.h>
#include <stdint.h>

// Problem constants
#define M_ROWS   16384      // B*S
#define E_DIM    768
#define NQ       8
#define FFN_DIM  3072
#define LN_EPS   1e-5f

// ---------------------------------------------------------------------------
// Scratch (device globals: no cudaMalloc allowed)
// ---------------------------------------------------------------------------
__device__ __half g_cx [M_ROWS * E_DIM];    // cos(x + rx), fp16
__device__ float  g_z  [M_ROWS * E_DIM];    // pre-LN1
__device__ float  g_x1 [M_ROWS * E_DIM];    // LN1 output
__device__ float  g_q  [M_ROWS * NQ];
__device__ __half g_h  [M_ROWS * FFN_DIM];  // relu(q@W1+b1), fp16
__device__ float  g_f  [M_ROWS * E_DIM];    // pre-LN2
__device__ __half g_WcT[E_DIM * E_DIM];     // Wc^T, fp16
__device__ __half g_W2T[E_DIM * FFN_DIM];   // W2^T, fp16

// ---------------------------------------------------------------------------
// Helpers (baseline PTX only — compute_103 has no 'a' features)
// ---------------------------------------------------------------------------
__device__ __forceinline__ uint32_t smem_u32(const void* p) {
    uint32_t a;
    asm("{ .reg .u64 t; cvta.to.shared.u64 t, %1; cvt.u32.u64 %0, t; }"
        : "=r"(a) : "l"(p));
    return a;
}

__device__ __forceinline__ void cp16(uint32_t s, const void* g) {
    asm volatile("cp.async.ca.shared.global [%0], [%1], 16;" :: "r"(s), "l"(g));
}
#define CP_COMMIT() asm volatile("cp.async.commit_group;" ::: "memory")
#define CP_WAIT(n)  asm volatile("cp.async.wait_group %0;" :: "n"(n) : "memory")

__device__ __forceinline__ void ldsm4(uint32_t* r, uint32_t addr) {
    asm volatile("ldmatrix.sync.aligned.m8n8.x4.shared.b16 {%0,%1,%2,%3}, [%4];"
        : "=r"(r[0]), "=r"(r[1]), "=r"(r[2]), "=r"(r[3]) : "r"(addr));
}

__device__ __forceinline__ void mma16816(float* c, const uint32_t* a,
                                         uint32_t b0, uint32_t b1) {
    asm volatile(
        "mma.sync.aligned.m16n8k16.row.col.f32.f16.f16.f32 "
        "{%0,%1,%2,%3}, {%4,%5,%6,%7}, {%8,%9}, {%0,%1,%2,%3};"
        : "+f"(c[0]), "+f"(c[1]), "+f"(c[2]), "+f"(c[3])
        : "r"(a[0]), "r"(a[1]), "r"(a[2]), "r"(a[3]), "r"(b0), "r"(b1));
}

// ---------------------------------------------------------------------------
// fp16 tensor-core GEMM (round-9 config — at the mma.sync rate ceiling):
//   C[M, 768] = A[M, K] @ Bt[768, K]^T + bias + res
// CTA: 256 threads (8 warps, 4x2), tile 256(M) x 128(N), warp tile 64x64.
// KT=64, 3-stage cp.async pipeline, ONE __syncthreads per K-tile,
// fragment double-buffering across the 4 k16 steps.
// ---------------------------------------------------------------------------
#define KT        64
#define ROW_B     144                       // smem row stride bytes
#define A_BYTES   (256 * ROW_B)             // 36864
#define B_BYTES   (128 * ROW_B)             // 18432
#define STAGE_BYTES (A_BYTES + B_BYTES)     // 55296
#define NSTAGE    3
#define SMEM_BYTES  (NSTAGE * STAGE_BYTES)  // 165888

__global__ void __launch_bounds__(256, 1)
gemm_mma_kernel(const __half* __restrict__ A, const __half* __restrict__ Bt,
                const float* __restrict__ bias, const float* __restrict__ res,
                float* __restrict__ C, int K, int NK)
{
    extern __shared__ char smem[];
    const uint32_t sbase = smem_u32(smem);

    const int tid  = threadIdx.x;
    const int w    = tid >> 5, lane = tid & 31;
    const int g    = lane >> 2, tg = lane & 3;
    const int row0 = blockIdx.y * 256;
    const int col0 = blockIdx.x * 128;
    const int wm   = (w >> 1) * 64;         // 0,64,128,192
    const int wn   = (w & 1) * 64;          // 0,64

    const int lrow = lane & 15;
    const int lsel = lane >> 4;

    const int crow = tid >> 3;              // 0..31
    const int cchk = tid & 7;               // 0..7
    const __half* Ag = A  + (size_t)(row0 + crow) * K + cchk * 8;
    const __half* Bg = Bt + (size_t)(col0 + crow) * K + cchk * 8;

    float acc[4][8][4];
    #pragma unroll
    for (int i = 0; i < 4; i++)
        #pragma unroll
        for (int j = 0; j < 8; j++)
            #pragma unroll
            for (int v = 0; v < 4; v++) acc[i][j][v] = 0.f;

    const uint32_t so = (uint32_t)crow * ROW_B + (uint32_t)cchk * 16u;

    auto issue = [&](int kt) {
        const int s = kt % NSTAGE;
        const int k0 = kt * KT;
        const uint32_t sA = sbase + (uint32_t)s * STAGE_BYTES;
        const uint32_t sB = sA + A_BYTES;
        #pragma unroll
        for (int p = 0; p < 8; p++)
            cp16(sA + so + (uint32_t)(32 * p) * ROW_B,
                 Ag + (size_t)(32 * p) * K + k0);
        #pragma unroll
        for (int p = 0; p < 4; p++)
            cp16(sB + so + (uint32_t)(32 * p) * ROW_B,
                 Bg + (size_t)(32 * p) * K + k0);
        CP_COMMIT();
    };

    issue(0); issue(1);

    uint32_t af[2][4][4];
    uint32_t bf[2][4][4];

    for (int kt = 0; kt < NK; kt++) {
        const int s = kt % NSTAGE;
        CP_WAIT(1);
        __syncthreads();
        if (kt + 2 < NK) issue(kt + 2); else CP_COMMIT();

        const uint32_t sA = sbase + (uint32_t)s * STAGE_BYTES;
        const uint32_t sB = sA + A_BYTES;
        const uint32_t aB = sA + (uint32_t)(wm + lrow) * ROW_B + (uint32_t)lsel * 16u;
        const uint32_t bB = sB + (uint32_t)(wn + lrow) * ROW_B + (uint32_t)lsel * 16u;

        #pragma unroll
        for (int i = 0; i < 4; i++)
            ldsm4(af[0][i], aB + (uint32_t)(16 * i) * ROW_B);
        #pragma unroll
        for (int jj = 0; jj < 4; jj++)
            ldsm4(bf[0][jj], bB + (uint32_t)(16 * jj) * ROW_B);

        #pragma unroll
        for (int t2 = 0; t2 < 4; t2++) {
            const int cur = t2 & 1, nxt = cur ^ 1;
            if (t2 < 3) {
                const uint32_t ko = (uint32_t)(t2 + 1) * 32u;
                #pragma unroll
                for (int i = 0; i < 4; i++)
                    ldsm4(af[nxt][i], aB + (uint32_t)(16 * i) * ROW_B + ko);
                #pragma unroll
                for (int jj = 0; jj < 4; jj++)
                    ldsm4(bf[nxt][jj], bB + (uint32_t)(16 * jj) * ROW_B + ko);
            }
            #pragma unroll
            for (int i = 0; i < 4; i++)
                #pragma unroll
                for (int j = 0; j < 8; j++) {
                    const int jj = j >> 1, odd = j & 1;
                    mma16816(acc[i][j], af[cur][i],
                             bf[cur][jj][odd], bf[cur][jj][2 + odd]);
                }
        }
    }

    // Epilogue: + bias + res -> C
    float2 bj[8];
    #pragma unroll
    for (int j = 0; j < 8; j++)
        bj[j] = *(const float2*)(bias + col0 + wn + 8 * j + 2 * tg);

    #pragma unroll
    for (int i = 0; i < 4; i++) {
        const int r0 = row0 + wm + 16 * i + g;
        const int r1 = r0 + 8;
        #pragma unroll
        for (int j = 0; j < 8; j++) {
            const int c = col0 + wn + 8 * j + 2 * tg;
            const size_t i0 = (size_t)r0 * E_DIM + c;
            const size_t i1 = (size_t)r1 * E_DIM + c;
            float2 rv0 = *(const float2*)(res + i0);
            float2 rv1 = *(const float2*)(res + i1);
            float2 o0, o1;
            o0.x = acc[i][j][0] + bj[j].x + rv0.x;
            o0.y = acc[i][j][1] + bj[j].y + rv0.y;
            o1.x = acc[i][j][2] + bj[j].x + rv1.x;
            o1.y = acc[i][j][3] + bj[j].y + rv1.y;
            *(float2*)(C + i0) = o0;
            *(float2*)(C + i1) = o1;
        }
    }
}

// ---------------------------------------------------------------------------
// cos(x + rx) precompute -> fp16 (8 elems/thread, 16B store)
// ---------------------------------------------------------------------------
__global__ void __launch_bounds__(256)
cosx_kernel(const float* __restrict__ x, const float* __restrict__ rx,
            __half* __restrict__ cx)
{
    const int i = blockIdx.x * 256 + threadIdx.x;
    float4 v0 = ((const float4*)x)[2 * i];
    float4 v1 = ((const float4*)x)[2 * i + 1];
    const int e = (i * 8) & 63;
    __half2 h[4];
    h[0] = __floats2half2_rn(cosf(v0.x + rx[e + 0]), cosf(v0.y + rx[e + 1]));
    h[1] = __floats2half2_rn(cosf(v0.z + rx[e + 2]), cosf(v0.w + rx[e + 3]));
    h[2] = __floats2half2_rn(cosf(v1.x + rx[e + 4]), cosf(v1.y + rx[e + 5]));
    h[3] = __floats2half2_rn(cosf(v1.z + rx[e + 6]), cosf(v1.w + rx[e + 7]));
    ((uint4*)cx)[i] = *(const uint4*)h;
}

// ---------------------------------------------------------------------------
// Transpose: in R x C (fp32) -> out C x R (fp16)
// ---------------------------------------------------------------------------
__global__ void __launch_bounds__(256)
transpose_kernel(const float* __restrict__ in, __half* __restrict__ out, int R, int C)
{
    __shared__ float t[32][33];
    const int c0 = blockIdx.x * 32, r0 = blockIdx.y * 32;
    #pragma unroll
    for (int j = 0; j < 4; j++)
        t[threadIdx.y + j * 8][threadIdx.x] =
            in[(size_t)(r0 + threadIdx.y + j * 8) * C + (c0 + threadIdx.x)];
    __syncthreads();
    #pragma unroll
    for (int j = 0; j < 4; j++)
        out[(size_t)(c0 + threadIdx.y + j * 8) * R + (r0 + threadIdx.x)] =
            __float2half_rn(t[threadIdx.x][threadIdx.y + j * 8]);
}

// ---------------------------------------------------------------------------
// Row LayerNorm over E=768 — ONE WARP PER ROW, barrier-free.
// 256 threads = 8 rows per block. Lane holds 6 float4 (cols lane*4 + i*128).
// If WRITE_Q: lanes 0-1 own cols 0..7 -> q = cos(y)*cos(ry).
// ---------------------------------------------------------------------------
template <bool WRITE_Q>
__global__ void __launch_bounds__(256)
ln_kernel(const float* __restrict__ in, const float* __restrict__ g,
          const float* __restrict__ b, const float* __restrict__ ry,
          float* __restrict__ out, float* __restrict__ q)
{
    const int wid  = threadIdx.x >> 5;
    const int lane = threadIdx.x & 31;
    const int m    = blockIdx.x * 8 + wid;
    const float* row = in + (size_t)m * E_DIM;

    float4 v[6];
    float s = 0.f, ss = 0.f;
    #pragma unroll
    for (int i = 0; i < 6; i++) {
        v[i] = *(const float4*)(row + lane * 4 + i * 128);
        s  += v[i].x + v[i].y + v[i].z + v[i].w;
        ss += v[i].x * v[i].x + v[i].y * v[i].y
            + v[i].z * v[i].z + v[i].w * v[i].w;
    }
    #pragma unroll
    for (int o = 16; o > 0; o >>= 1) {
        s  += __shfl_xor_sync(0xffffffffu, s,  o);
        ss += __shfl_xor_sync(0xffffffffu, ss, o);
    }

    const float mu  = s * (1.f / E_DIM);
    const float var = ss * (1.f / E_DIM) - mu * mu;
    const float inv = rsqrtf(var + LN_EPS);

    float* orow = out + (size_t)m * E_DIM;
    #pragma unroll
    for (int i = 0; i < 6; i++) {
        const int c = lane * 4 + i * 128;
        const float4 gv = *(const float4*)(g + c);
        const float4 bv = *(const float4*)(b + c);
        float4 y;
        y.x = (v[i].x - mu) * inv * gv.x + bv.x;
        y.y = (v[i].y - mu) * inv * gv.y + bv.y;
        y.z = (v[i].z - mu) * inv * gv.z + bv.z;
        y.w = (v[i].w - mu) * inv * gv.w + bv.w;
        *(float4*)(orow + c) = y;
        if (WRITE_Q && i == 0 && lane < 2) {
            const int c0 = lane * 4;
            q[(size_t)m * NQ + c0 + 0] = cosf(y.x) * cosf(ry[c0 + 0]);
            q[(size_t)m * NQ + c0 + 1] = cosf(y.y) * cosf(ry[c0 + 1]);
            q[(size_t)m * NQ + c0 + 2] = cosf(y.z) * cosf(ry[c0 + 2]);
            q[(size_t)m * NQ + c0 + 3] = cosf(y.w) * cosf(ry[c0 + 3]);
        }
    }
}

// ---------------------------------------------------------------------------
// FFN first layer (tiled): h = relu(q @ W1 + b1) -> fp16.
// ---------------------------------------------------------------------------
__global__ void __launch_bounds__(256)
ffn1_kernel(const float* __restrict__ q, const float* __restrict__ W1,
            const float* __restrict__ b1, __half* __restrict__ h)
{
    __shared__ float w1s[NQ][1024];
    __shared__ float b1s[1024];
    __shared__ float qs[256][NQ];

    const int col0 = blockIdx.x * 1024;
    const int m0   = blockIdx.y * 256;
    const int tid  = threadIdx.x;

    #pragma unroll
    for (int i = 0; i < NQ; i++)
        *(float4*)&w1s[i][tid * 4] =
            *(const float4*)(W1 + (size_t)i * FFN_DIM + col0 + tid * 4);
    *(float4*)&b1s[tid * 4] = *(const float4*)(b1 + col0 + tid * 4);
    {
        const int r = tid;
        float2 q01 = *(const float2*)(q + (size_t)(m0 + r) * NQ + 0);
        float2 q23 = *(const float2*)(q + (size_t)(m0 + r) * NQ + 2);
        float2 q45 = *(const float2*)(q + (size_t)(m0 + r) * NQ + 4);
        float2 q67 = *(const float2*)(q + (size_t)(m0 + r) * NQ + 6);
        qs[r][0] = q01.x; qs[r][1] = q01.y;
        qs[r][2] = q23.x; qs[r][3] = q23.y;
        qs[r][4] = q45.x; qs[r][5] = q45.y;
        qs[r][6] = q67.x; qs[r][7] = q67.y;
    }
    __syncthreads();

    float4 wr[NQ];
    #pragma unroll
    for (int i = 0; i < NQ; i++) wr[i] = *(float4*)&w1s[i][tid * 4];
    const float4 bb = *(float4*)&b1s[tid * 4];

    __half* hp = h + (size_t)m0 * FFN_DIM + col0 + tid * 4;
    for (int r = 0; r < 256; r++) {
        float4 acc = bb;
        #pragma unroll
        for (int i = 0; i < NQ; i++) {
            const float qv = qs[r][i];
            acc.x = fmaf(qv, wr[i].x, acc.x);
            acc.y = fmaf(qv, wr[i].y, acc.y);
            acc.z = fmaf(qv, wr[i].z, acc.z);
            acc.w = fmaf(qv, wr[i].w, acc.w);
        }
        __half2 p0 = __floats2half2_rn(fmaxf(acc.x, 0.f), fmaxf(acc.y, 0.f));
        __half2 p1 = __floats2half2_rn(fmaxf(acc.z, 0.f), fmaxf(acc.w, 0.f));
        uint2 pk = make_uint2(*(uint32_t*)&p0, *(uint32_t*)&p1);
        *(uint2*)(hp + (size_t)r * FFN_DIM) = pk;
    }
}

// ---------------------------------------------------------------------------
// Launch
// ---------------------------------------------------------------------------
extern "C" void kernel_launch(void* const* d_in, const int* in_sizes, int n_in,
                              void* d_out, int out_size)
{
    const float* x   = (const float*)d_in[0];
    const float* rx  = (const float*)d_in[1];
    const float* ry  = (const float*)d_in[2];
    const float* Wc  = (const float*)d_in[3];
    const float* bc  = (const float*)d_in[4];
    const float* W1  = (const float*)d_in[5];
    const float* b1  = (const float*)d_in[6];
    const float* W2  = (const float*)d_in[7];
    const float* b2  = (const float*)d_in[8];
    const float* g1  = (const float*)d_in[9];
    const float* be1 = (const float*)d_in[10];
    const float* g2  = (const float*)d_in[11];
    const float* be2 = (const float*)d_in[12];
    float* out = (float*)d_out;

    __half *cx, *h, *WcT, *W2T;
    float *z, *x1, *q, *f;
    cudaGetSymbolAddress((void**)&cx,  g_cx);
    cudaGetSymbolAddress((void**)&z,   g_z);
    cudaGetSymbolAddress((void**)&x1,  g_x1);
    cudaGetSymbolAddress((void**)&q,   g_q);
    cudaGetSymbolAddress((void**)&h,   g_h);
    cudaGetSymbolAddress((void**)&f,   g_f);
    cudaGetSymbolAddress((void**)&WcT, g_WcT);
    cudaGetSymbolAddress((void**)&W2T, g_W2T);

    cudaFuncSetAttribute(gemm_mma_kernel,
                         cudaFuncAttributeMaxDynamicSharedMemorySize, SMEM_BYTES);

    // 0) weight transposes (fp16) + cos precompute (fp16)
    transpose_kernel<<<dim3(E_DIM / 32, E_DIM / 32), dim3(32, 8)>>>(Wc, WcT, E_DIM, E_DIM);
    transpose_kernel<<<dim3(E_DIM / 32, FFN_DIM / 32), dim3(32, 8)>>>(W2, W2T, FFN_DIM, E_DIM);
    cosx_kernel<<<(M_ROWS * E_DIM / 8) / 256, 256>>>(x, rx, cx);

    // 1) z = cos(x+rx) @ Wc + bc + x        (fp16 mma + ldmatrix)
    gemm_mma_kernel<<<dim3(E_DIM / 128, M_ROWS / 256), 256, SMEM_BYTES>>>(
        cx, WcT, bc, x, z, E_DIM, E_DIM / KT);

    // 2) x1 = LN(z); q = cos(x1[:, :8]) * cos(ry)   (warp-per-row)
    ln_kernel<true><<<M_ROWS / 8, 256>>>(z, g1, be1, ry, x1, q);

    // 3) h = relu(q @ W1 + b1)  -> fp16
    ffn1_kernel<<<dim3(FFN_DIM / 1024, M_ROWS / 256), 256>>>(q, W1, b1, h);

    // 4) f = h @ W2 + b2 + x1               (fp16 mma + ldmatrix)
    gemm_mma_kernel<<<dim3(E_DIM / 128, M_ROWS / 256), 256, SMEM_BYTES>>>(
        h, W2T, b2, x1, f, FFN_DIM, FFN_DIM / KT);

    // 5) out = LN(f)                        (warp-per-row)
    ln_kernel<false><<<M_ROWS / 8, 256>>>(f, g2, be2, nullptr, out, nullptr);
}